// round 1
// baseline (speedup 1.0000x reference)
#include <cuda_runtime.h>
#include <cstdint>

// HeteLinear: out[n] = x[n] @ W[x_type[n]] + b[x_type[n]]
// N=262144, IN=OUT=128, T=8, fp32.
//
// Strategy: grid (chunks x types). Each block caches W[t] in smem, compacts
// matching rows of its chunk, and computes 8 rows per warp per iteration
// using packed f32x2 FMAs (fma.rn.f32x2 -> SASS FFMA2, 2x fp32 throughput).

#define CHUNK     2048
#define NTHREADS  256
#define NWARPS    8
#define DIM_IN    128
#define DIM_OUT   128

// smem layout (floats): Ws[128*128] | xps[8 warps * 1024] | list[2048 u16] | cnt
#define SMEM_W_FLOATS   (DIM_IN * DIM_OUT)          // 16384
#define SMEM_X_FLOATS   (NWARPS * 1024)             // 8192
#define SMEM_BYTES      ((SMEM_W_FLOATS + SMEM_X_FLOATS) * 4 + CHUNK * 2 + 16)

__device__ __forceinline__ unsigned long long pack2(float lo, float hi) {
    unsigned long long r;
    asm("mov.b64 %0, {%1, %2};" : "=l"(r) : "f"(lo), "f"(hi));
    return r;
}
__device__ __forceinline__ void unpack2(unsigned long long v, float &lo, float &hi) {
    asm("mov.b64 {%0, %1}, %2;" : "=f"(lo), "=f"(hi) : "l"(v));
}
__device__ __forceinline__ unsigned long long fma2(unsigned long long a,
                                                   unsigned long long b,
                                                   unsigned long long c) {
    unsigned long long d;
    asm("fma.rn.f32x2 %0, %1, %2, %3;" : "=l"(d) : "l"(a), "l"(b), "l"(c));
    return d;
}

__global__ __launch_bounds__(NTHREADS, 2)
void hete_linear_kernel(const float* __restrict__ x,
                        const int*   __restrict__ x_type,
                        const float* __restrict__ W,
                        const float* __restrict__ b,
                        float*       __restrict__ out)
{
    extern __shared__ float smem[];
    float*    Ws   = smem;                                   // [128][128]
    float*    xpsA = smem + SMEM_W_FLOATS;                   // per-warp 1024 floats
    uint16_t* list = (uint16_t*)(smem + SMEM_W_FLOATS + SMEM_X_FLOATS);
    int*      cnt  = (int*)(list + CHUNK);

    const int tid   = threadIdx.x;
    const int warp  = tid >> 5;
    const int lane  = tid & 31;
    const int t     = blockIdx.y;          // type 0..7
    const int base  = blockIdx.x * CHUNK;  // chunk row base

    if (tid == 0) *cnt = 0;
    __syncthreads();

    // ---- Load W[t] into smem (64 KB), coalesced float4 ----
    {
        const float4* Wg  = (const float4*)(W + (size_t)t * DIM_IN * DIM_OUT);
        float4*       Wsv = (float4*)Ws;
        #pragma unroll 4
        for (int i = tid; i < SMEM_W_FLOATS / 4; i += NTHREADS)
            Wsv[i] = Wg[i];
    }

    // ---- Compact matching rows (warp-aggregated) ----
    for (int i = tid; i < CHUNK; i += NTHREADS) {
        bool m = (x_type[base + i] == t);
        unsigned mask = __ballot_sync(0xffffffffu, m);
        int pos = 0;
        if (lane == 0 && mask) pos = atomicAdd(cnt, __popc(mask));
        pos = __shfl_sync(0xffffffffu, pos, 0);
        if (m)
            list[pos + __popc(mask & ((1u << lane) - 1u))] = (uint16_t)i;
    }
    __syncthreads();
    const int count = *cnt;

    // per-lane bias: outputs j = lane*4 .. lane*4+3
    const float4 bias = ((const float4*)(b + (size_t)t * DIM_OUT))[lane];

    float* xps = xpsA + warp * 1024;  // 4 row-pairs x 128 k x 2 floats

    // ---- Main loop: 8 rows per warp-iteration ----
    for (int g = warp; g * 8 < count; g += NWARPS) {
        const int start = g * 8;
        const int nr    = min(8, count - start);

        int rows[8];
        __syncwarp();
        #pragma unroll
        for (int rr = 0; rr < 8; rr++) {
            int li  = start + (rr < nr ? rr : 0);
            int row = base + (int)list[li];
            rows[rr] = row;
            // coalesced: warp loads the full 128-float row (lane -> float4)
            float4 v = ((const float4*)x)[(size_t)row * 32 + lane];
            int p = rr >> 1, h = rr & 1;
            int kb = lane * 4;
            xps[p * 256 + (kb + 0) * 2 + h] = v.x;
            xps[p * 256 + (kb + 1) * 2 + h] = v.y;
            xps[p * 256 + (kb + 2) * 2 + h] = v.z;
            xps[p * 256 + (kb + 3) * 2 + h] = v.w;
        }
        __syncwarp();

        unsigned long long acc[4][4];  // [output j][row pair p]
        #pragma unroll
        for (int j = 0; j < 4; j++)
            #pragma unroll
            for (int p = 0; p < 4; p++)
                acc[j][p] = 0ull;

        #pragma unroll 8
        for (int k = 0; k < DIM_IN; k++) {
            // W row k, this lane's 4 output columns (conflict-free LDS.128)
            float4 w4 = ((const float4*)Ws)[k * 32 + lane];
            unsigned long long wd[4];
            wd[0] = pack2(w4.x, w4.x);
            wd[1] = pack2(w4.y, w4.y);
            wd[2] = pack2(w4.z, w4.z);
            wd[3] = pack2(w4.w, w4.w);
            unsigned long long xv[4];
            #pragma unroll
            for (int p = 0; p < 4; p++)
                xv[p] = *(const unsigned long long*)&xps[p * 256 + k * 2]; // bcast LDS.64
            #pragma unroll
            for (int j = 0; j < 4; j++)
                #pragma unroll
                for (int p = 0; p < 4; p++)
                    acc[j][p] = fma2(wd[j], xv[p], acc[j][p]);
        }

        // ---- Epilogue: bias + coalesced store ----
        #pragma unroll
        for (int rr = 0; rr < 8; rr++) {
            if (rr < nr) {
                int p = rr >> 1, h = rr & 1;
                float lo, hi;
                float4 o;
                unpack2(acc[0][p], lo, hi); o.x = (h ? hi : lo) + bias.x;
                unpack2(acc[1][p], lo, hi); o.y = (h ? hi : lo) + bias.y;
                unpack2(acc[2][p], lo, hi); o.z = (h ? hi : lo) + bias.z;
                unpack2(acc[3][p], lo, hi); o.w = (h ? hi : lo) + bias.w;
                ((float4*)out)[(size_t)rows[rr] * 32 + lane] = o;
            }
        }
    }
}

extern "C" void kernel_launch(void* const* d_in, const int* in_sizes, int n_in,
                              void* d_out, int out_size)
{
    const float* x      = (const float*)d_in[0];
    const int*   x_type = (const int*)d_in[1];
    const float* W      = (const float*)d_in[2];
    const float* b      = (const float*)d_in[3];
    float*       out    = (float*)d_out;

    const int N = in_sizes[1];            // number of rows (x_type count)
    const int n_chunks = N / CHUNK;       // 262144 / 2048 = 128

    cudaFuncSetAttribute(hete_linear_kernel,
                         cudaFuncAttributeMaxDynamicSharedMemorySize, SMEM_BYTES);

    dim3 grid(n_chunks, 8);
    hete_linear_kernel<<<grid, NTHREADS, SMEM_BYTES>>>(x, x_type, W, b, out);
}